// round 13
// baseline (speedup 1.0000x reference)
#include <cuda_runtime.h>
#include <cuda_fp16.h>
#include <math.h>
#include <stdint.h>
#include <string.h>

#define B_SZ 4
#define T_SEQ 2048
#define D_MODEL 1024
#define NH 16
#define HD 64
#define QKV_STRIDE 3072
#define M_ROWS 8192

// ---------------------------------------------------------------------------
// Scratch (device globals: no dynamic allocation allowed)
// ---------------------------------------------------------------------------
__device__ __half g_xh   [(size_t)M_ROWS * D_MODEL];
__device__ __half g_wqkvh[(size_t)D_MODEL * QKV_STRIDE];
__device__ __half g_woh  [(size_t)D_MODEL * D_MODEL];
__device__ __half g_qkvh [(size_t)M_ROWS * QKV_STRIDE];
__device__ __half g_ctxh [(size_t)M_ROWS * D_MODEL];

// ---------------------------------------------------------------------------
// PTX helpers
// ---------------------------------------------------------------------------
__device__ __forceinline__ float ex2(float x) {
    float r; asm("ex2.approx.ftz.f32 %0, %1;" : "=f"(r) : "f"(x)); return r;
}
__device__ __forceinline__ uint32_t h2u(__half2 h) {
    uint32_t u; memcpy(&u, &h, 4); return u;
}
__device__ __forceinline__ void mma_f16(float* c, const uint32_t* a, const uint32_t* b) {
    asm volatile(
        "mma.sync.aligned.m16n8k16.row.col.f32.f16.f16.f32 "
        "{%0,%1,%2,%3},{%4,%5,%6,%7},{%8,%9},{%0,%1,%2,%3};"
        : "+f"(c[0]), "+f"(c[1]), "+f"(c[2]), "+f"(c[3])
        : "r"(a[0]), "r"(a[1]), "r"(a[2]), "r"(a[3]), "r"(b[0]), "r"(b[1]));
}
__device__ __forceinline__ void ldsm_x4(uint32_t* r, uint32_t addr) {
    asm volatile("ldmatrix.sync.aligned.m8n8.x4.shared.b16 {%0,%1,%2,%3}, [%4];"
                 : "=r"(r[0]), "=r"(r[1]), "=r"(r[2]), "=r"(r[3]) : "r"(addr));
}
__device__ __forceinline__ void ldsm_x4_t(uint32_t* r, uint32_t addr) {
    asm volatile("ldmatrix.sync.aligned.m8n8.x4.trans.shared.b16 {%0,%1,%2,%3}, [%4];"
                 : "=r"(r[0]), "=r"(r[1]), "=r"(r[2]), "=r"(r[3]) : "r"(addr));
}
__device__ __forceinline__ void cpa16(uint32_t dst, const void* src) {
    asm volatile("cp.async.cg.shared.global [%0], [%1], 16;" :: "r"(dst), "l"(src));
}
__device__ __forceinline__ void cpa_commit() { asm volatile("cp.async.commit_group;"); }
template<int N> __device__ __forceinline__ void cpa_wait() {
    asm volatile("cp.async.wait_group %0;" :: "n"(N));
}
__device__ __forceinline__ uint32_t s2u(const void* p) {
    return (uint32_t)__cvta_generic_to_shared(p);
}

// ---------------------------------------------------------------------------
// fp32 -> fp16 conversions (x + W_qkv on main; W_o forked)
// ---------------------------------------------------------------------------
#define N2_X (8388608 / 2)
#define N2_WQKV (3145728 / 2)
#define N2_WO (1048576 / 2)
__global__ void conv_xw(const float* __restrict__ x, const float* __restrict__ wqkv,
                        __half2* __restrict__ xo, __half2* __restrict__ wqkvo) {
    int i = blockIdx.x * blockDim.x + threadIdx.x;
    if (i < N2_X) {
        float2 v = ((const float2*)x)[i];
        xo[i] = __floats2half2_rn(v.x, v.y);
    }
    int j = i - N2_X;
    if (j >= 0 && j < N2_WQKV) {
        float2 v = ((const float2*)wqkv)[j];
        wqkvo[j] = __floats2half2_rn(v.x, v.y);
    }
}
__global__ void conv_wo(const float* __restrict__ wo, __half2* __restrict__ woo) {
    int i = blockIdx.x * blockDim.x + threadIdx.x;
    if (i < N2_WO) {
        float2 v = ((const float2*)wo)[i];
        woo[i] = __floats2half2_rn(v.x, v.y);
    }
}

// ---------------------------------------------------------------------------
// fp16 GEMM + bias (R11 config): 128x128x64 tile, 128 threads, 64x64 warp
// tiles, 3-stage cp.async.
// ---------------------------------------------------------------------------
#define G_BM 128
#define G_BN 128
#define G_BK 64
#define LDA_B 144
#define LDB_B 272
#define A_STG (G_BM * LDA_B)
#define B_STG (G_BK * LDB_B)
#define STG_B (A_STG + B_STG)
#define G_SMEM (3 * STG_B)

template<int OUT_HALF>
__global__ __launch_bounds__(128, 2) void gemm_h(
    const __half* __restrict__ A, const __half* __restrict__ Bm,
    const float* __restrict__ bias, void* __restrict__ Cout,
    int M, int N, int K)
{
    extern __shared__ char smem[];
    const int tid  = threadIdx.x;
    const int lane = tid & 31, w = tid >> 5;
    const int g = lane >> 2, t = lane & 3;
    const int lrow = lane & 7, seg = lane >> 3;
    const int wm = (w >> 1) * 64, wn = (w & 1) * 64;
    const int brow = blockIdx.y * G_BM, bcol = blockIdx.x * G_BN;
    const int NIT = K / G_BK;

    auto prefetch = [&](int it, int s) {
        char* As = smem + s * STG_B;
        char* Bs = As + A_STG;
        const int k0 = it * G_BK;
        #pragma unroll
        for (int i = 0; i < 8; i++) {
            int idx = tid + i * 128;
            int r = idx >> 3, c = idx & 7;
            cpa16(s2u(As + r * LDA_B + c * 16),
                  A + (size_t)(brow + r) * K + k0 + c * 8);
        }
        #pragma unroll
        for (int i = 0; i < 8; i++) {
            int idx = tid + i * 128;
            int r = idx >> 4, c = idx & 15;
            cpa16(s2u(Bs + r * LDB_B + c * 16),
                  Bm + (size_t)(k0 + r) * N + bcol + c * 8);
        }
        cpa_commit();
    };

    float acc[4][8][4];
    #pragma unroll
    for (int mt = 0; mt < 4; mt++)
        #pragma unroll
        for (int nt = 0; nt < 8; nt++)
            #pragma unroll
            for (int i = 0; i < 4; i++) acc[mt][nt][i] = 0.f;

    prefetch(0, 0);
    prefetch(1, 1);

    for (int it = 0; it < NIT; it++) {
        cpa_wait<1>();
        __syncthreads();
        if (it + 2 < NIT) prefetch(it + 2, (it + 2) % 3);

        char* As = smem + (it % 3) * STG_B;
        char* Bs = As + A_STG;

        #pragma unroll
        for (int ks = 0; ks < 4; ks++) {
            uint32_t af[4][4], bf[8][2];
            #pragma unroll
            for (int mt = 0; mt < 4; mt++) {
                int row = wm + mt * 16 + ((seg & 1) ? 8 : 0) + lrow;
                int kk  = ks * 16 + ((seg >> 1) ? 8 : 0);
                ldsm_x4(af[mt], s2u(As + row * LDA_B + kk * 2));
            }
            #pragma unroll
            for (int np = 0; np < 4; np++) {
                uint32_t r4[4];
                int kr = ks * 16 + ((seg & 1) ? 8 : 0) + lrow;
                int nc = wn + (np * 2 + (seg >> 1)) * 8;
                ldsm_x4_t(r4, s2u(Bs + kr * LDB_B + nc * 2));
                bf[np * 2][0] = r4[0]; bf[np * 2][1] = r4[1];
                bf[np * 2 + 1][0] = r4[2]; bf[np * 2 + 1][1] = r4[3];
            }
            #pragma unroll
            for (int mt = 0; mt < 4; mt++)
                #pragma unroll
                for (int nt = 0; nt < 8; nt++)
                    mma_f16(acc[mt][nt], af[mt], bf[nt]);
        }
        __syncthreads();
    }

    #pragma unroll
    for (int mt = 0; mt < 4; mt++) {
        int r0 = brow + wm + mt * 16 + g;
        #pragma unroll
        for (int nt = 0; nt < 8; nt++) {
            int c = bcol + wn + nt * 8 + 2 * t;
            float2 bv = *(const float2*)&bias[c];
            if (OUT_HALF) {
                __half2* C = (__half2*)Cout;
                C[((size_t)r0 * N + c) >> 1] =
                    __floats2half2_rn(acc[mt][nt][0] + bv.x, acc[mt][nt][1] + bv.y);
                C[((size_t)(r0 + 8) * N + c) >> 1] =
                    __floats2half2_rn(acc[mt][nt][2] + bv.x, acc[mt][nt][3] + bv.y);
            } else {
                float* C = (float*)Cout;
                *(float2*)&C[(size_t)r0 * N + c] =
                    make_float2(acc[mt][nt][0] + bv.x, acc[mt][nt][1] + bv.y);
                *(float2*)&C[(size_t)(r0 + 8) * N + c] =
                    make_float2(acc[mt][nt][2] + bv.x, acc[mt][nt][3] + bv.y);
            }
        }
    }
}

// ---------------------------------------------------------------------------
// FlashAttention-2, fp16 mma (exact R8/R11 inner loop), batch-offset param.
// ---------------------------------------------------------------------------
#define LDQ_B 144
#define Q_SZ  (64 * LDQ_B)
#define KV_SZ (2 * Q_SZ)
#define AT_SMEM (Q_SZ + 2 * KV_SZ + 2 * 256)

__global__ __launch_bounds__(128) void attn_h(
    const __half* __restrict__ qkv, const int* __restrict__ kpm,
    __half* __restrict__ ctx, int b_off)
{
    extern __shared__ char smem[];
    char* Qs  = smem;
    char* KV0 = smem + Q_SZ;
    char* MB  = smem + Q_SZ + 2 * KV_SZ;

    const int tid = threadIdx.x, lane = tid & 31, w = tid >> 5;
    const int g = lane >> 2, t = lane & 3;
    const int lrow = lane & 7, seg = lane >> 3;
    const int b = blockIdx.z + b_off, h = blockIdx.y;
    const int qb = blockIdx.x * 64;
    const int ntiles = blockIdx.x + 1;

    const __half* kvb = qkv + (size_t)b * T_SEQ * QKV_STRIDE + h * HD;
    const int* mrow = kpm + b * T_SEQ;

    auto prefetch = [&](int kt, int s) {
        char* K = KV0 + s * KV_SZ;
        const int kb = kt * 64;
        #pragma unroll
        for (int i = 0; i < 8; i++) {
            int idx = tid + i * 128;
            int isV = idx >> 9;
            int r = (idx & 511) >> 3, c = idx & 7;
            cpa16(s2u(K + isV * Q_SZ + r * LDQ_B + c * 16),
                  kvb + (size_t)(kb + r) * QKV_STRIDE + D_MODEL + isV * D_MODEL + c * 8);
        }
        if (tid < 16)
            cpa16(s2u(MB + s * 256 + tid * 16), mrow + kb + tid * 4);
        cpa_commit();
    };

    prefetch(0, 0);

    #pragma unroll
    for (int i = 0; i < 4; i++) {
        int idx = tid + i * 128;
        int r = idx >> 3, c = idx & 7;
        *(uint4*)(Qs + r * LDQ_B + c * 16) =
            *(const uint4*)(kvb + (size_t)(qb + r) * QKV_STRIDE + c * 8);
    }
    __syncthreads();
    uint32_t qf[4][4];
    #pragma unroll
    for (int kc = 0; kc < 4; kc++) {
        int row = w * 16 + ((seg & 1) ? 8 : 0) + lrow;
        int kk  = kc * 16 + ((seg >> 1) ? 8 : 0);
        ldsm_x4(qf[kc], s2u(Qs + row * LDQ_B + kk * 2));
    }

    float o[8][4];
    #pragma unroll
    for (int nt = 0; nt < 8; nt++)
        #pragma unroll
        for (int i = 0; i < 4; i++) o[nt][i] = 0.f;

    float m0 = -1e30f, m1 = -1e30f, l0 = 0.f, l1 = 0.f;
    const int q0 = qb + w * 16 + g, q1 = q0 + 8;
    const float SL = 0.125f * 1.4426950408889634f;

    for (int kt = 0; kt < ntiles; kt++) {
        cpa_wait<0>();
        __syncthreads();
        if (kt + 1 < ntiles) prefetch(kt + 1, (kt + 1) & 1);

        char* Ks = KV0 + (kt & 1) * KV_SZ;
        char* Vs = Ks + Q_SZ;
        const int* mb = (const int*)(MB + (kt & 1) * 256);
        const int kb = kt * 64;

        float s[8][4];
        #pragma unroll
        for (int nt = 0; nt < 8; nt++)
            s[nt][0] = s[nt][1] = s[nt][2] = s[nt][3] = 0.f;
        #pragma unroll
        for (int kc = 0; kc < 4; kc++) {
            #pragma unroll
            for (int np = 0; np < 4; np++) {
                uint32_t r4[4];
                int krow = np * 16 + ((seg >> 1) ? 8 : 0) + lrow;
                int kk   = kc * 16 + ((seg & 1) ? 8 : 0);
                ldsm_x4(r4, s2u(Ks + krow * LDQ_B + kk * 2));
                uint32_t b0[2] = {r4[0], r4[1]}, b1[2] = {r4[2], r4[3]};
                mma_f16(s[np * 2],     qf[kc], b0);
                mma_f16(s[np * 2 + 1], qf[kc], b1);
            }
        }

        float mx0 = -1e30f, mx1 = -1e30f;
        #pragma unroll
        for (int nt = 0; nt < 8; nt++) {
            int cl = nt * 8 + 2 * t;
            float a0 = mb[cl]     ? -1e30f : 0.f;
            float a1 = mb[cl + 1] ? -1e30f : 0.f;
            int k0c = kb + cl, k1c = k0c + 1;
            float v00 = s[nt][0] * SL + a0; if (k0c > q0) v00 = -1e30f;
            float v01 = s[nt][1] * SL + a1; if (k1c > q0) v01 = -1e30f;
            float v10 = s[nt][2] * SL + a0; if (k0c > q1) v10 = -1e30f;
            float v11 = s[nt][3] * SL + a1; if (k1c > q1) v11 = -1e30f;
            s[nt][0] = v00; s[nt][1] = v01; s[nt][2] = v10; s[nt][3] = v11;
            mx0 = fmaxf(mx0, fmaxf(v00, v01));
            mx1 = fmaxf(mx1, fmaxf(v10, v11));
        }
        mx0 = fmaxf(mx0, __shfl_xor_sync(0xffffffffu, mx0, 1));
        mx0 = fmaxf(mx0, __shfl_xor_sync(0xffffffffu, mx0, 2));
        mx1 = fmaxf(mx1, __shfl_xor_sync(0xffffffffu, mx1, 1));
        mx1 = fmaxf(mx1, __shfl_xor_sync(0xffffffffu, mx1, 2));

        const float nm0 = fmaxf(m0, mx0), nm1 = fmaxf(m1, mx1);
        const float f0 = ex2(m0 - nm0), f1 = ex2(m1 - nm1);

        uint32_t plo[8], phi[8];
        float sum0 = 0.f, sum1 = 0.f;
        #pragma unroll
        for (int nt = 0; nt < 8; nt++) {
            float p00 = ex2(s[nt][0] - nm0);
            float p01 = ex2(s[nt][1] - nm0);
            float p10 = ex2(s[nt][2] - nm1);
            float p11 = ex2(s[nt][3] - nm1);
            sum0 += p00 + p01; sum1 += p10 + p11;
            plo[nt] = h2u(__floats2half2_rn(p00, p01));
            phi[nt] = h2u(__floats2half2_rn(p10, p11));
        }
        sum0 += __shfl_xor_sync(0xffffffffu, sum0, 1);
        sum0 += __shfl_xor_sync(0xffffffffu, sum0, 2);
        sum1 += __shfl_xor_sync(0xffffffffu, sum1, 1);
        sum1 += __shfl_xor_sync(0xffffffffu, sum1, 2);
        l0 = l0 * f0 + sum0;
        l1 = l1 * f1 + sum1;
        #pragma unroll
        for (int nt = 0; nt < 8; nt++) {
            o[nt][0] *= f0; o[nt][1] *= f0; o[nt][2] *= f1; o[nt][3] *= f1;
        }
        m0 = nm0; m1 = nm1;

        #pragma unroll
        for (int kc = 0; kc < 4; kc++) {
            uint32_t af[4] = {plo[kc * 2], phi[kc * 2], plo[kc * 2 + 1], phi[kc * 2 + 1]};
            #pragma unroll
            for (int np = 0; np < 4; np++) {
                uint32_t r4[4];
                int krow = kc * 16 + ((seg & 1) ? 8 : 0) + lrow;
                int nc   = (np * 2 + (seg >> 1)) * 8;
                ldsm_x4_t(r4, s2u(Vs + krow * LDQ_B + nc * 2));
                uint32_t b0[2] = {r4[0], r4[1]}, b1[2] = {r4[2], r4[3]};
                mma_f16(o[np * 2],     af, b0);
                mma_f16(o[np * 2 + 1], af, b1);
            }
        }
    }

    const float i0 = 1.f / l0, i1 = 1.f / l1;
    __half* op = ctx + (size_t)b * T_SEQ * D_MODEL + h * HD;
    #pragma unroll
    for (int nt = 0; nt < 8; nt++) {
        int c = nt * 8 + 2 * t;
        *(__half2*)(op + (size_t)q0 * D_MODEL + c) =
            __floats2half2_rn(o[nt][0] * i0, o[nt][1] * i0);
        *(__half2*)(op + (size_t)q1 * D_MODEL + c) =
            __floats2half2_rn(o[nt][2] * i1, o[nt][3] * i1);
    }
}

// ---------------------------------------------------------------------------
// Launch: fork/join graph.
//   main: conv_xw -> gemm1 -> attn(b0,1) -[e1]-> attn(b2,3) -> gemm2b -> wait(e3)
//   s1:   wait(e0) -> conv_wo -> wait(e1) -> gemm2a -[e3]
// ---------------------------------------------------------------------------
extern "C" void kernel_launch(void* const* d_in, const int* in_sizes, int n_in,
                              void* d_out, int out_size)
{
    const float* x = nullptr; const float* W_qkv = nullptr;
    const float* b_qkv = nullptr; const float* W_o = nullptr;
    const float* b_o = nullptr; const int* kpm = nullptr;
    for (int i = 0; i < n_in; i++) {
        switch (in_sizes[i]) {
            case 8388608: x     = (const float*)d_in[i]; break;
            case 3145728: W_qkv = (const float*)d_in[i]; break;
            case 3072:    b_qkv = (const float*)d_in[i]; break;
            case 1048576: W_o   = (const float*)d_in[i]; break;
            case 1024:    b_o   = (const float*)d_in[i]; break;
            case 8192:    kpm   = (const int*)d_in[i]; break;
            default: break;
        }
    }
    float* out = (float*)d_out;

    __half *xh, *wqkvh, *woh, *qkvh, *ctxh;
    cudaGetSymbolAddress((void**)&xh, g_xh);
    cudaGetSymbolAddress((void**)&wqkvh, g_wqkvh);
    cudaGetSymbolAddress((void**)&woh, g_woh);
    cudaGetSymbolAddress((void**)&qkvh, g_qkvh);
    cudaGetSymbolAddress((void**)&ctxh, g_ctxh);

    static cudaStream_t s1;
    static cudaEvent_t e0, e1, e3;
    static int init_done = 0;
    if (!init_done) {
        cudaFuncSetAttribute(gemm_h<1>, cudaFuncAttributeMaxDynamicSharedMemorySize, G_SMEM);
        cudaFuncSetAttribute(gemm_h<0>, cudaFuncAttributeMaxDynamicSharedMemorySize, G_SMEM);
        cudaFuncSetAttribute(attn_h, cudaFuncAttributeMaxDynamicSharedMemorySize, AT_SMEM);
        cudaStreamCreateWithFlags(&s1, cudaStreamNonBlocking);
        cudaEventCreateWithFlags(&e0, cudaEventDisableTiming);
        cudaEventCreateWithFlags(&e1, cudaEventDisableTiming);
        cudaEventCreateWithFlags(&e3, cudaEventDisableTiming);
        init_done = 1;
    }

    // fork for W_o conversion (independent of main chain until gemm2)
    cudaEventRecord(e0, 0);
    cudaStreamWaitEvent(s1, e0, 0);
    conv_wo<<<(N2_WO + 255) / 256, 256, 0, s1>>>(W_o, (__half2*)woh);

    // main chain
    conv_xw<<<(N2_X + N2_WQKV + 255) / 256, 256>>>(x, W_qkv,
                                                   (__half2*)xh, (__half2*)wqkvh);
    {
        dim3 grid(QKV_STRIDE / G_BN, M_ROWS / G_BM);
        gemm_h<1><<<grid, 128, G_SMEM>>>(xh, wqkvh, b_qkv, qkvh,
                                         M_ROWS, QKV_STRIDE, D_MODEL);
    }
    // attention first half: batches 0,1
    {
        dim3 grid(T_SEQ / 64, NH, 2);
        attn_h<<<grid, 128, AT_SMEM>>>(qkvh, kpm, ctxh, 0);
    }
    cudaEventRecord(e1, 0);
    // attention second half: batches 2,3 (main stream)
    {
        dim3 grid(T_SEQ / 64, NH, 2);
        attn_h<<<grid, 128, AT_SMEM>>>(qkvh, kpm, ctxh, 2);
    }
    // side stream: gemm2 on rows of batches 0,1 once e1 fires (conv_wo ordered before on s1)
    cudaStreamWaitEvent(s1, e1, 0);
    {
        dim3 grid(D_MODEL / G_BN, (M_ROWS / 2) / G_BM);
        gemm_h<0><<<grid, 128, G_SMEM, s1>>>(ctxh, woh, b_o, out,
                                             M_ROWS / 2, D_MODEL, D_MODEL);
    }
    cudaEventRecord(e3, s1);
    // main: gemm2 on rows of batches 2,3
    {
        dim3 grid(D_MODEL / G_BN, (M_ROWS / 2) / G_BM);
        gemm_h<0><<<grid, 128, G_SMEM>>>(ctxh + (size_t)(M_ROWS / 2) * D_MODEL,
                                         woh, b_o,
                                         out + (size_t)(M_ROWS / 2) * D_MODEL,
                                         M_ROWS / 2, D_MODEL, D_MODEL);
    }
    // join
    cudaStreamWaitEvent(0, e3, 0);
}

// round 15
// speedup vs baseline: 1.0348x; 1.0348x over previous
#include <cuda_runtime.h>
#include <cuda_fp16.h>
#include <math.h>
#include <stdint.h>
#include <string.h>

#define B_SZ 4
#define T_SEQ 2048
#define D_MODEL 1024
#define NH 16
#define HD 64
#define QKV_STRIDE 3072
#define M_ROWS 8192

// ---------------------------------------------------------------------------
// Scratch (device globals: no dynamic allocation allowed)
// ---------------------------------------------------------------------------
__device__ __half g_xh   [(size_t)M_ROWS * D_MODEL];
__device__ __half g_wqkvh[(size_t)D_MODEL * QKV_STRIDE];
__device__ __half g_woh  [(size_t)D_MODEL * D_MODEL];
__device__ __half g_qkvh [(size_t)M_ROWS * QKV_STRIDE];
__device__ __half g_ctxh [(size_t)M_ROWS * D_MODEL];

// ---------------------------------------------------------------------------
// PTX helpers
// ---------------------------------------------------------------------------
__device__ __forceinline__ float ex2(float x) {
    float r; asm("ex2.approx.ftz.f32 %0, %1;" : "=f"(r) : "f"(x)); return r;
}
__device__ __forceinline__ uint32_t h2u(__half2 h) {
    uint32_t u; memcpy(&u, &h, 4); return u;
}
__device__ __forceinline__ void mma_f16(float* c, const uint32_t* a, const uint32_t* b) {
    asm volatile(
        "mma.sync.aligned.m16n8k16.row.col.f32.f16.f16.f32 "
        "{%0,%1,%2,%3},{%4,%5,%6,%7},{%8,%9},{%0,%1,%2,%3};"
        : "+f"(c[0]), "+f"(c[1]), "+f"(c[2]), "+f"(c[3])
        : "r"(a[0]), "r"(a[1]), "r"(a[2]), "r"(a[3]), "r"(b[0]), "r"(b[1]));
}
__device__ __forceinline__ void ldsm_x4(uint32_t* r, uint32_t addr) {
    asm volatile("ldmatrix.sync.aligned.m8n8.x4.shared.b16 {%0,%1,%2,%3}, [%4];"
                 : "=r"(r[0]), "=r"(r[1]), "=r"(r[2]), "=r"(r[3]) : "r"(addr));
}
__device__ __forceinline__ void ldsm_x4_t(uint32_t* r, uint32_t addr) {
    asm volatile("ldmatrix.sync.aligned.m8n8.x4.trans.shared.b16 {%0,%1,%2,%3}, [%4];"
                 : "=r"(r[0]), "=r"(r[1]), "=r"(r[2]), "=r"(r[3]) : "r"(addr));
}
__device__ __forceinline__ void cpa16(uint32_t dst, const void* src) {
    asm volatile("cp.async.cg.shared.global [%0], [%1], 16;" :: "r"(dst), "l"(src));
}
__device__ __forceinline__ void cpa_commit() { asm volatile("cp.async.commit_group;"); }
template<int N> __device__ __forceinline__ void cpa_wait() {
    asm volatile("cp.async.wait_group %0;" :: "n"(N));
}
__device__ __forceinline__ uint32_t s2u(const void* p) {
    return (uint32_t)__cvta_generic_to_shared(p);
}

// ---------------------------------------------------------------------------
// fp32 -> fp16 conversion, all three tensors in one launch
// ---------------------------------------------------------------------------
#define N2_X (8388608 / 2)
#define N2_WQKV (3145728 / 2)
#define N2_WO (1048576 / 2)
__global__ void conv_all(const float* __restrict__ x, const float* __restrict__ wqkv,
                         const float* __restrict__ wo, __half2* __restrict__ xo,
                         __half2* __restrict__ wqkvo, __half2* __restrict__ woo) {
    int i = blockIdx.x * blockDim.x + threadIdx.x;
    if (i < N2_X) {
        float2 v = ((const float2*)x)[i];
        xo[i] = __floats2half2_rn(v.x, v.y);
    }
    int j = i - N2_X;
    if (j >= 0 && j < N2_WQKV) {
        float2 v = ((const float2*)wqkv)[j];
        wqkvo[j] = __floats2half2_rn(v.x, v.y);
    }
    int k = j - N2_WQKV;
    if (k >= 0 && k < N2_WO) {
        float2 v = ((const float2*)wo)[k];
        woo[k] = __floats2half2_rn(v.x, v.y);
    }
}
#define CONV_TOTAL (N2_X + N2_WQKV + N2_WO)

// ---------------------------------------------------------------------------
// fp16 GEMM + bias (R11 config): 128x128x64 tile, 128 threads, 64x64 warp
// tiles, 3-stage cp.async.
// ---------------------------------------------------------------------------
#define G_BM 128
#define G_BN 128
#define G_BK 64
#define LDA_B 144
#define LDB_B 272
#define A_STG (G_BM * LDA_B)
#define B_STG (G_BK * LDB_B)
#define STG_B (A_STG + B_STG)
#define G_SMEM (3 * STG_B)

template<int OUT_HALF>
__global__ __launch_bounds__(128, 2) void gemm_h(
    const __half* __restrict__ A, const __half* __restrict__ Bm,
    const float* __restrict__ bias, void* __restrict__ Cout,
    int M, int N, int K)
{
    extern __shared__ char smem[];
    const int tid  = threadIdx.x;
    const int lane = tid & 31, w = tid >> 5;
    const int g = lane >> 2, t = lane & 3;
    const int lrow = lane & 7, seg = lane >> 3;
    const int wm = (w >> 1) * 64, wn = (w & 1) * 64;
    const int brow = blockIdx.y * G_BM, bcol = blockIdx.x * G_BN;
    const int NIT = K / G_BK;

    auto prefetch = [&](int it, int s) {
        char* As = smem + s * STG_B;
        char* Bs = As + A_STG;
        const int k0 = it * G_BK;
        #pragma unroll
        for (int i = 0; i < 8; i++) {
            int idx = tid + i * 128;
            int r = idx >> 3, c = idx & 7;
            cpa16(s2u(As + r * LDA_B + c * 16),
                  A + (size_t)(brow + r) * K + k0 + c * 8);
        }
        #pragma unroll
        for (int i = 0; i < 8; i++) {
            int idx = tid + i * 128;
            int r = idx >> 4, c = idx & 15;
            cpa16(s2u(Bs + r * LDB_B + c * 16),
                  Bm + (size_t)(k0 + r) * N + bcol + c * 8);
        }
        cpa_commit();
    };

    float acc[4][8][4];
    #pragma unroll
    for (int mt = 0; mt < 4; mt++)
        #pragma unroll
        for (int nt = 0; nt < 8; nt++)
            #pragma unroll
            for (int i = 0; i < 4; i++) acc[mt][nt][i] = 0.f;

    prefetch(0, 0);
    prefetch(1, 1);

    for (int it = 0; it < NIT; it++) {
        cpa_wait<1>();
        __syncthreads();
        if (it + 2 < NIT) prefetch(it + 2, (it + 2) % 3);

        char* As = smem + (it % 3) * STG_B;
        char* Bs = As + A_STG;

        #pragma unroll
        for (int ks = 0; ks < 4; ks++) {
            uint32_t af[4][4], bf[8][2];
            #pragma unroll
            for (int mt = 0; mt < 4; mt++) {
                int row = wm + mt * 16 + ((seg & 1) ? 8 : 0) + lrow;
                int kk  = ks * 16 + ((seg >> 1) ? 8 : 0);
                ldsm_x4(af[mt], s2u(As + row * LDA_B + kk * 2));
            }
            #pragma unroll
            for (int np = 0; np < 4; np++) {
                uint32_t r4[4];
                int kr = ks * 16 + ((seg & 1) ? 8 : 0) + lrow;
                int nc = wn + (np * 2 + (seg >> 1)) * 8;
                ldsm_x4_t(r4, s2u(Bs + kr * LDB_B + nc * 2));
                bf[np * 2][0] = r4[0]; bf[np * 2][1] = r4[1];
                bf[np * 2 + 1][0] = r4[2]; bf[np * 2 + 1][1] = r4[3];
            }
            #pragma unroll
            for (int mt = 0; mt < 4; mt++)
                #pragma unroll
                for (int nt = 0; nt < 8; nt++)
                    mma_f16(acc[mt][nt], af[mt], bf[nt]);
        }
        __syncthreads();
    }

    #pragma unroll
    for (int mt = 0; mt < 4; mt++) {
        int r0 = brow + wm + mt * 16 + g;
        #pragma unroll
        for (int nt = 0; nt < 8; nt++) {
            int c = bcol + wn + nt * 8 + 2 * t;
            float2 bv = *(const float2*)&bias[c];
            if (OUT_HALF) {
                __half2* C = (__half2*)Cout;
                C[((size_t)r0 * N + c) >> 1] =
                    __floats2half2_rn(acc[mt][nt][0] + bv.x, acc[mt][nt][1] + bv.y);
                C[((size_t)(r0 + 8) * N + c) >> 1] =
                    __floats2half2_rn(acc[mt][nt][2] + bv.x, acc[mt][nt][3] + bv.y);
            } else {
                float* C = (float*)Cout;
                *(float2*)&C[(size_t)r0 * N + c] =
                    make_float2(acc[mt][nt][0] + bv.x, acc[mt][nt][1] + bv.y);
                *(float2*)&C[(size_t)(r0 + 8) * N + c] =
                    make_float2(acc[mt][nt][2] + bv.x, acc[mt][nt][3] + bv.y);
            }
        }
    }
}

// ---------------------------------------------------------------------------
// FlashAttention-2, fp16 mma, P in registers, 2-stage cp.async K/V.
// R11 inner loop; launch_bounds(128,4) to cap regs at 128 (4 CTAs/SM),
// heaviest-first q-block order (LPT scheduling).
// ---------------------------------------------------------------------------
#define LDQ_B 144            // 64 halves + 8 pad
#define Q_SZ  (64 * LDQ_B)   // 9216
#define KV_SZ (2 * Q_SZ)     // 18432
#define AT_SMEM (Q_SZ + 2 * KV_SZ + 2 * 256)

__global__ __launch_bounds__(128, 4) void attn_h(
    const __half* __restrict__ qkv, const int* __restrict__ kpm,
    __half* __restrict__ ctx)
{
    extern __shared__ char smem[];
    char* Qs  = smem;
    char* KV0 = smem + Q_SZ;
    char* MB  = smem + Q_SZ + 2 * KV_SZ;

    const int tid = threadIdx.x, lane = tid & 31, w = tid >> 5;
    const int g = lane >> 2, t = lane & 3;
    const int lrow = lane & 7, seg = lane >> 3;
    const int b = blockIdx.z, h = blockIdx.y;
    const int qblk = (int)gridDim.x - 1 - (int)blockIdx.x;  // heaviest first
    const int qb = qblk * 64;
    const int ntiles = qblk + 1;

    const __half* kvb = qkv + (size_t)b * T_SEQ * QKV_STRIDE + h * HD;
    const int* mrow = kpm + b * T_SEQ;

    auto prefetch = [&](int kt, int s) {
        char* K = KV0 + s * KV_SZ;
        const int kb = kt * 64;
        #pragma unroll
        for (int i = 0; i < 8; i++) {
            int idx = tid + i * 128;
            int isV = idx >> 9;
            int r = (idx & 511) >> 3, c = idx & 7;
            cpa16(s2u(K + isV * Q_SZ + r * LDQ_B + c * 16),
                  kvb + (size_t)(kb + r) * QKV_STRIDE + D_MODEL + isV * D_MODEL + c * 8);
        }
        if (tid < 16)
            cpa16(s2u(MB + s * 256 + tid * 16), mrow + kb + tid * 4);
        cpa_commit();
    };

    prefetch(0, 0);

    #pragma unroll
    for (int i = 0; i < 4; i++) {
        int idx = tid + i * 128;
        int r = idx >> 3, c = idx & 7;
        *(uint4*)(Qs + r * LDQ_B + c * 16) =
            *(const uint4*)(kvb + (size_t)(qb + r) * QKV_STRIDE + c * 8);
    }
    __syncthreads();
    uint32_t qf[4][4];
    #pragma unroll
    for (int kc = 0; kc < 4; kc++) {
        int row = w * 16 + ((seg & 1) ? 8 : 0) + lrow;
        int kk  = kc * 16 + ((seg >> 1) ? 8 : 0);
        ldsm_x4(qf[kc], s2u(Qs + row * LDQ_B + kk * 2));
    }

    float o[8][4];
    #pragma unroll
    for (int nt = 0; nt < 8; nt++)
        #pragma unroll
        for (int i = 0; i < 4; i++) o[nt][i] = 0.f;

    float m0 = -1e30f, m1 = -1e30f, l0 = 0.f, l1 = 0.f;
    const int q0 = qb + w * 16 + g, q1 = q0 + 8;
    const float SL = 0.125f * 1.4426950408889634f;

    for (int kt = 0; kt < ntiles; kt++) {
        cpa_wait<0>();
        __syncthreads();
        if (kt + 1 < ntiles) prefetch(kt + 1, (kt + 1) & 1);

        char* Ks = KV0 + (kt & 1) * KV_SZ;
        char* Vs = Ks + Q_SZ;
        const int* mb = (const int*)(MB + (kt & 1) * 256);
        const int kb = kt * 64;

        float s[8][4];
        #pragma unroll
        for (int nt = 0; nt < 8; nt++)
            s[nt][0] = s[nt][1] = s[nt][2] = s[nt][3] = 0.f;
        #pragma unroll
        for (int kc = 0; kc < 4; kc++) {
            #pragma unroll
            for (int np = 0; np < 4; np++) {
                uint32_t r4[4];
                int krow = np * 16 + ((seg >> 1) ? 8 : 0) + lrow;
                int kk   = kc * 16 + ((seg & 1) ? 8 : 0);
                ldsm_x4(r4, s2u(Ks + krow * LDQ_B + kk * 2));
                uint32_t b0[2] = {r4[0], r4[1]}, b1[2] = {r4[2], r4[3]};
                mma_f16(s[np * 2],     qf[kc], b0);
                mma_f16(s[np * 2 + 1], qf[kc], b1);
            }
        }

        float mx0 = -1e30f, mx1 = -1e30f;
        #pragma unroll
        for (int nt = 0; nt < 8; nt++) {
            int cl = nt * 8 + 2 * t;
            float a0 = mb[cl]     ? -1e30f : 0.f;
            float a1 = mb[cl + 1] ? -1e30f : 0.f;
            int k0c = kb + cl, k1c = k0c + 1;
            float v00 = s[nt][0] * SL + a0; if (k0c > q0) v00 = -1e30f;
            float v01 = s[nt][1] * SL + a1; if (k1c > q0) v01 = -1e30f;
            float v10 = s[nt][2] * SL + a0; if (k0c > q1) v10 = -1e30f;
            float v11 = s[nt][3] * SL + a1; if (k1c > q1) v11 = -1e30f;
            s[nt][0] = v00; s[nt][1] = v01; s[nt][2] = v10; s[nt][3] = v11;
            mx0 = fmaxf(mx0, fmaxf(v00, v01));
            mx1 = fmaxf(mx1, fmaxf(v10, v11));
        }
        mx0 = fmaxf(mx0, __shfl_xor_sync(0xffffffffu, mx0, 1));
        mx0 = fmaxf(mx0, __shfl_xor_sync(0xffffffffu, mx0, 2));
        mx1 = fmaxf(mx1, __shfl_xor_sync(0xffffffffu, mx1, 1));
        mx1 = fmaxf(mx1, __shfl_xor_sync(0xffffffffu, mx1, 2));

        const float nm0 = fmaxf(m0, mx0), nm1 = fmaxf(m1, mx1);
        const float f0 = ex2(m0 - nm0), f1 = ex2(m1 - nm1);

        uint32_t plo[8], phi[8];
        float sum0 = 0.f, sum1 = 0.f;
        #pragma unroll
        for (int nt = 0; nt < 8; nt++) {
            float p00 = ex2(s[nt][0] - nm0);
            float p01 = ex2(s[nt][1] - nm0);
            float p10 = ex2(s[nt][2] - nm1);
            float p11 = ex2(s[nt][3] - nm1);
            sum0 += p00 + p01; sum1 += p10 + p11;
            plo[nt] = h2u(__floats2half2_rn(p00, p01));
            phi[nt] = h2u(__floats2half2_rn(p10, p11));
        }
        sum0 += __shfl_xor_sync(0xffffffffu, sum0, 1);
        sum0 += __shfl_xor_sync(0xffffffffu, sum0, 2);
        sum1 += __shfl_xor_sync(0xffffffffu, sum1, 1);
        sum1 += __shfl_xor_sync(0xffffffffu, sum1, 2);
        l0 = l0 * f0 + sum0;
        l1 = l1 * f1 + sum1;
        #pragma unroll
        for (int nt = 0; nt < 8; nt++) {
            o[nt][0] *= f0; o[nt][1] *= f0; o[nt][2] *= f1; o[nt][3] *= f1;
        }
        m0 = nm0; m1 = nm1;

        #pragma unroll
        for (int kc = 0; kc < 4; kc++) {
            uint32_t af[4] = {plo[kc * 2], phi[kc * 2], plo[kc * 2 + 1], phi[kc * 2 + 1]};
            #pragma unroll
            for (int np = 0; np < 4; np++) {
                uint32_t r4[4];
                int krow = kc * 16 + ((seg & 1) ? 8 : 0) + lrow;
                int nc   = (np * 2 + (seg >> 1)) * 8;
                ldsm_x4_t(r4, s2u(Vs + krow * LDQ_B + nc * 2));
                uint32_t b0[2] = {r4[0], r4[1]}, b1[2] = {r4[2], r4[3]};
                mma_f16(o[np * 2],     af, b0);
                mma_f16(o[np * 2 + 1], af, b1);
            }
        }
    }

    const float i0 = 1.f / l0, i1 = 1.f / l1;
    __half* op = ctx + (size_t)b * T_SEQ * D_MODEL + h * HD;
    #pragma unroll
    for (int nt = 0; nt < 8; nt++) {
        int c = nt * 8 + 2 * t;
        *(__half2*)(op + (size_t)q0 * D_MODEL + c) =
            __floats2half2_rn(o[nt][0] * i0, o[nt][1] * i0);
        *(__half2*)(op + (size_t)q1 * D_MODEL + c) =
            __floats2half2_rn(o[nt][2] * i1, o[nt][3] * i1);
    }
}

// ---------------------------------------------------------------------------
// Launch (serial R11 chain)
// ---------------------------------------------------------------------------
extern "C" void kernel_launch(void* const* d_in, const int* in_sizes, int n_in,
                              void* d_out, int out_size)
{
    const float* x = nullptr; const float* W_qkv = nullptr;
    const float* b_qkv = nullptr; const float* W_o = nullptr;
    const float* b_o = nullptr; const int* kpm = nullptr;
    for (int i = 0; i < n_in; i++) {
        switch (in_sizes[i]) {
            case 8388608: x     = (const float*)d_in[i]; break;
            case 3145728: W_qkv = (const float*)d_in[i]; break;
            case 3072:    b_qkv = (const float*)d_in[i]; break;
            case 1048576: W_o   = (const float*)d_in[i]; break;
            case 1024:    b_o   = (const float*)d_in[i]; break;
            case 8192:    kpm   = (const int*)d_in[i]; break;
            default: break;
        }
    }
    float* out = (float*)d_out;

    __half *xh, *wqkvh, *woh, *qkvh, *ctxh;
    cudaGetSymbolAddress((void**)&xh, g_xh);
    cudaGetSymbolAddress((void**)&wqkvh, g_wqkvh);
    cudaGetSymbolAddress((void**)&woh, g_woh);
    cudaGetSymbolAddress((void**)&qkvh, g_qkvh);
    cudaGetSymbolAddress((void**)&ctxh, g_ctxh);

    static int attr_done = 0;
    if (!attr_done) {
        cudaFuncSetAttribute(gemm_h<1>, cudaFuncAttributeMaxDynamicSharedMemorySize, G_SMEM);
        cudaFuncSetAttribute(gemm_h<0>, cudaFuncAttributeMaxDynamicSharedMemorySize, G_SMEM);
        cudaFuncSetAttribute(attn_h, cudaFuncAttributeMaxDynamicSharedMemorySize, AT_SMEM);
        attr_done = 1;
    }

    // 0) fp32 -> fp16 conversions (single launch)
    conv_all<<<(CONV_TOTAL + 255) / 256, 256>>>(x, W_qkv, W_o,
                                                (__half2*)xh, (__half2*)wqkvh,
                                                (__half2*)woh);

    // 1) QKV projection (fp16 out)
    {
        dim3 grid(QKV_STRIDE / G_BN, M_ROWS / G_BM);
        gemm_h<1><<<grid, 128, G_SMEM>>>(xh, wqkvh, b_qkv, qkvh,
                                         M_ROWS, QKV_STRIDE, D_MODEL);
    }
    // 2) FlashAttention
    {
        dim3 grid(T_SEQ / 64, NH, B_SZ);
        attn_h<<<grid, 128, AT_SMEM>>>(qkvh, kpm, ctxh);
    }
    // 3) Output projection (fp32 out)
    {
        dim3 grid(D_MODEL / G_BN, M_ROWS / G_BM);
        gemm_h<0><<<grid, 128, G_SMEM>>>(ctxh, woh, b_o, out,
                                         M_ROWS, D_MODEL, D_MODEL);
    }
}